// round 1
// baseline (speedup 1.0000x reference)
#include <cuda_runtime.h>

#define Nn 256
#define Dd 64
#define Cc 32
#define Rr 16
#define Oo 32

// lse[d,o,r] = max_{ij} logits + log(sum_ij exp(logits - max))
__device__ float g_lse[Dd * Oo * Rr];

__global__ void lse_kernel(const float* __restrict__ logits) {
    __shared__ float red[8];
    __shared__ float bmax;
    const int b = blockIdx.x;  // flat (d,o,r); logits[d,o,r,:,:] is 1024 contiguous floats
    const float4 v = reinterpret_cast<const float4*>(logits)[(size_t)b * 256 + threadIdx.x];
    float m = fmaxf(fmaxf(v.x, v.y), fmaxf(v.z, v.w));
#pragma unroll
    for (int o = 16; o; o >>= 1) m = fmaxf(m, __shfl_xor_sync(0xffffffffu, m, o));
    if ((threadIdx.x & 31) == 0) red[threadIdx.x >> 5] = m;
    __syncthreads();
    if (threadIdx.x == 0) {
        float t = red[0];
#pragma unroll
        for (int k = 1; k < 8; k++) t = fmaxf(t, red[k]);
        bmax = t;
    }
    __syncthreads();
    m = bmax;
    float s = __expf(v.x - m) + __expf(v.y - m) + __expf(v.z - m) + __expf(v.w - m);
#pragma unroll
    for (int o = 16; o; o >>= 1) s += __shfl_xor_sync(0xffffffffu, s, o);
    __syncthreads();  // red[] reuse
    if ((threadIdx.x & 31) == 0) red[threadIdx.x >> 5] = s;
    __syncthreads();
    if (threadIdx.x == 0) {
        float t = 0.f;
#pragma unroll
        for (int k = 0; k < 8; k++) t += red[k];
        g_lse[b] = m + logf(t);
    }
}

// One CTA per (d, r, n_half). Computes out[n, d, :, r] for 128 n values.
// smem: Lp/Rp hold exp(x - rowmax), stored transposed [i][n] for conflict-free
// stride-1 n access. Weights streamed per-i as a 32x32 [j][o] slab, double-buffered,
// with softmax applied on the fly via precomputed lse.
__global__ __launch_bounds__(256, 2)
void einsum_kernel(const float* __restrict__ left, const float* __restrict__ right,
                   const float* __restrict__ logits, float* __restrict__ out) {
    __shared__ float Lp[Cc * 128];
    __shared__ float Rp[Cc * 128];
    __shared__ float Ws[2 * Cc * Oo];
    __shared__ float lmaxs[128];
    __shared__ float rmaxs[128];

    const int b = blockIdx.x;      // ((d * Rr) + r) * 2 + nh
    const int nh = b & 1;
    const int r = (b >> 1) & (Rr - 1);
    const int d = b >> 5;
    const int tid = threadIdx.x;

    // ---- phase 1: rowmax + exp, transposed into smem ----
    {
        const int n_loc = tid & 127;
        const int n = nh * 128 + n_loc;
        const float* src = (tid < 128) ? left : right;
        float* dst = (tid < 128) ? Lp : Rp;
        float* mx = (tid < 128) ? lmaxs : rmaxs;
        const float* p = src + (size_t)n * (Dd * Cc * Rr) + d * (Cc * Rr) + r;
        float m = -3.4e38f;
#pragma unroll
        for (int i = 0; i < Cc; i++) m = fmaxf(m, p[i * Rr]);
        mx[n_loc] = m;
#pragma unroll
        for (int i = 0; i < Cc; i++) dst[i * 128 + n_loc] = __expf(p[i * Rr] - m);
    }

    // ---- phase 2: register-tiled contraction (2 n x 8 o per thread) ----
    const int to = (tid & 3) * 8;        // o0: 4 o-groups of 8
    const int tn = (tid >> 2) * 2;       // n0: 64 n-groups of 2

    // weight staging responsibility: thread loads 4 consecutive j for one o
    const int wo = tid >> 3;             // 0..31
    const int wj = (tid & 7) * 4;        // 0,4,...,28
    const float* wsrc = logits + ((size_t)(d * Oo + wo) * Rr + r) * (Cc * Cc) + wj;
    const float lseo = g_lse[(d * Oo + wo) * Rr + r];

    float acc[2][8];
#pragma unroll
    for (int q = 0; q < 2; q++)
#pragma unroll
        for (int w = 0; w < 8; w++) acc[q][w] = 0.f;

    for (int i = 0; i < Cc; i++) {
        float* wsb = Ws + (i & 1) * (Cc * Oo);
        const float4 lv = *reinterpret_cast<const float4*>(wsrc + i * Cc);
        wsb[(wj + 0) * Oo + wo] = __expf(lv.x - lseo);
        wsb[(wj + 1) * Oo + wo] = __expf(lv.y - lseo);
        wsb[(wj + 2) * Oo + wo] = __expf(lv.z - lseo);
        wsb[(wj + 3) * Oo + wo] = __expf(lv.w - lseo);
        __syncthreads();

        const float2 l2 = *reinterpret_cast<const float2*>(&Lp[i * 128 + tn]);
#pragma unroll
        for (int j = 0; j < Cc; j++) {
            const float2 r2 = *reinterpret_cast<const float2*>(&Rp[j * 128 + tn]);
            const float4 wa = *reinterpret_cast<const float4*>(&wsb[j * Oo + to]);
            const float4 wb = *reinterpret_cast<const float4*>(&wsb[j * Oo + to + 4]);
            const float p0 = l2.x * r2.x;
            const float p1 = l2.y * r2.y;
            acc[0][0] = fmaf(p0, wa.x, acc[0][0]);
            acc[0][1] = fmaf(p0, wa.y, acc[0][1]);
            acc[0][2] = fmaf(p0, wa.z, acc[0][2]);
            acc[0][3] = fmaf(p0, wa.w, acc[0][3]);
            acc[0][4] = fmaf(p0, wb.x, acc[0][4]);
            acc[0][5] = fmaf(p0, wb.y, acc[0][5]);
            acc[0][6] = fmaf(p0, wb.z, acc[0][6]);
            acc[0][7] = fmaf(p0, wb.w, acc[0][7]);
            acc[1][0] = fmaf(p1, wa.x, acc[1][0]);
            acc[1][1] = fmaf(p1, wa.y, acc[1][1]);
            acc[1][2] = fmaf(p1, wa.z, acc[1][2]);
            acc[1][3] = fmaf(p1, wa.w, acc[1][3]);
            acc[1][4] = fmaf(p1, wb.x, acc[1][4]);
            acc[1][5] = fmaf(p1, wb.y, acc[1][5]);
            acc[1][6] = fmaf(p1, wb.z, acc[1][6]);
            acc[1][7] = fmaf(p1, wb.w, acc[1][7]);
        }
        __syncthreads();
    }

    // ---- epilogue: log + add maxes, store (N, D, O, R) layout ----
#pragma unroll
    for (int q = 0; q < 2; q++) {
        const int n_loc = tn + q;
        const int n = nh * 128 + n_loc;
        const float add = lmaxs[n_loc] + rmaxs[n_loc];
        float* ob = out + (size_t)n * (Dd * Oo * Rr) + d * (Oo * Rr) + r;
#pragma unroll
        for (int w = 0; w < 8; w++)
            ob[(to + w) * Rr] = __logf(acc[q][w]) + add;
    }
}

extern "C" void kernel_launch(void* const* d_in, const int* in_sizes, int n_in,
                              void* d_out, int out_size) {
    const float* left = (const float*)d_in[0];
    const float* right = (const float*)d_in[1];
    const float* logits = (const float*)d_in[2];
    float* out = (float*)d_out;

    lse_kernel<<<Dd * Oo * Rr, 256>>>(logits);
    einsum_kernel<<<Dd * Rr * 2, 256>>>(left, right, logits, out);
}